// round 8
// baseline (speedup 1.0000x reference)
#include <cuda_runtime.h>
#include <math.h>

#define NB 64
#define TT 1024
#define DD 512
#define HH 512
#define FH 2048    // 4*H
#define GRID_R 128 // recurrence blocks (1/SM, all co-resident)
#define NTHR 512   // threads per recurrence block (16 warps)
#define HS_STRIDE 68
#define NGRP 8     // barrier tree: 8 groups x 16 blocks

// Scratch: xw in [T, N, 4H] layout (512 MB), TRANSPOSED ping-pong h, barriers.
__device__ float g_xw[(size_t)NB * TT * FH];
__device__ float g_hT[2][HH * NB];     // [buf][k][n]
__device__ unsigned g_bar_grp[NGRP];
__device__ unsigned g_bar_root;

union F2 { float2 f; unsigned long long u; };

#define FMA2(d, a, b) \
    asm("fma.rn.f32x2 %0, %1, %2, %3;" : "=l"((d).u) : "l"((a).u), "l"((b).u), "l"((d).u))

__device__ __forceinline__ float tanh_fast(float x) {
    float y;
    asm("tanh.approx.f32 %0, %1;" : "=f"(y) : "f"(x));
    return y;
}
__device__ __forceinline__ float sigmoid_fast(float x) {
    return fmaf(tanh_fast(0.5f * x), 0.5f, 0.5f);
}

// Release-arrival and acquire-poll primitives (no MEMBAR needed).
__device__ __forceinline__ void red_release(unsigned* p) {
    asm volatile("red.release.gpu.global.add.u32 [%0], 1;" :: "l"(p) : "memory");
}
__device__ __forceinline__ unsigned ld_acquire(const unsigned* p) {
    unsigned v;
    asm volatile("ld.acquire.gpu.global.u32 %0, [%1];" : "=r"(v) : "l"(p) : "memory");
    return v;
}

// ---------------------------------------------------------------------------
// Transpose h0 [64][512] -> g_hT[1][k][n] (one-off, 128KB)
// ---------------------------------------------------------------------------
__global__ __launch_bounds__(256) void transpose_h0_kernel(const float* __restrict__ h0)
{
    int idx = blockIdx.x * 256 + threadIdx.x;   // 0..32767
    int n = idx >> 9;
    int k = idx & 511;
    g_hT[1][k * NB + n] = h0[idx];
}

// ---------------------------------------------------------------------------
// Phase 1: xw[t*64+n, j] = sum_k x[n*1024+t, k] * Wx[k, j] + b[j]
// fp32 SGEMM with packed f32x2 FMA: BM=128, BN=128, BK=8, 256 thr, 8x8/thr.
// Output rows written TRANSPOSED to [T, N] order for phase-2 locality.
// ---------------------------------------------------------------------------
__global__ __launch_bounds__(256) void sgemm_xw_kernel(
    const float* __restrict__ A,      // x    [65536, 512]
    const float* __restrict__ B,      // Wx   [512, 2048]
    const float* __restrict__ bias)   // b    [2048]
{
    __shared__ float As[8][128];
    __shared__ float Bs2[8][256];     // duplicated pairs (v, v)

    const int tid = threadIdx.x;
    const int bx = blockIdx.x;    // col block (0..15)
    const int by = blockIdx.y;    // row block (0..511)
    const int tx = tid & 15;
    const int ty = tid >> 4;

    // Reset phase-2 barrier counters (graph replays reuse device globals)
    if (bx == 0 && by == 0 && tid <= NGRP) {
        if (tid < NGRP) g_bar_grp[tid] = 0u;
        else g_bar_root = 0u;
    }

    const float* Ab = A + (size_t)by * 128 * DD;
    const float* Bb = B + bx * 128;

    F2 acc[4][8];                 // [row-pair][col]
    #pragma unroll
    for (int i = 0; i < 4; ++i)
        #pragma unroll
        for (int j = 0; j < 8; ++j)
            acc[i][j].u = 0ull;

    const int arow = tid >> 1;          // 0..127
    const int ac4  = (tid & 1) * 4;     // 0 or 4
    const int brow = tid >> 5;          // 0..7
    const int bc4  = (tid & 31) * 4;    // 0..124

    for (int kc = 0; kc < DD; kc += 8) {
        float4 av = *(const float4*)(Ab + (size_t)arow * DD + kc + ac4);
        float4 bv = *(const float4*)(Bb + (size_t)(kc + brow) * FH + bc4);
        As[ac4 + 0][arow] = av.x;
        As[ac4 + 1][arow] = av.y;
        As[ac4 + 2][arow] = av.z;
        As[ac4 + 3][arow] = av.w;
        *(float2*)&Bs2[brow][2 * (bc4 + 0)] = make_float2(bv.x, bv.x);
        *(float2*)&Bs2[brow][2 * (bc4 + 1)] = make_float2(bv.y, bv.y);
        *(float2*)&Bs2[brow][2 * (bc4 + 2)] = make_float2(bv.z, bv.z);
        *(float2*)&Bs2[brow][2 * (bc4 + 3)] = make_float2(bv.w, bv.w);
        __syncthreads();

        #pragma unroll
        for (int k = 0; k < 8; ++k) {
            float4 a0 = *(const float4*)&As[k][ty * 8];
            float4 a1 = *(const float4*)&As[k][ty * 8 + 4];
            F2 ra[4];
            ra[0].f = make_float2(a0.x, a0.y);
            ra[1].f = make_float2(a0.z, a0.w);
            ra[2].f = make_float2(a1.x, a1.y);
            ra[3].f = make_float2(a1.z, a1.w);
            #pragma unroll
            for (int j = 0; j < 8; ++j) {
                F2 rb = *(F2*)&Bs2[k][2 * (tx * 8 + j)];
                #pragma unroll
                for (int i = 0; i < 4; ++i)
                    FMA2(acc[i][j], ra[i], rb);
            }
        }
        __syncthreads();
    }

    float bb[8];
    #pragma unroll
    for (int j = 0; j < 8; ++j)
        bb[j] = bias[bx * 128 + tx * 8 + j];

    #pragma unroll
    for (int i = 0; i < 4; ++i) {
        #pragma unroll
        for (int half = 0; half < 2; ++half) {
            int r = by * 128 + ty * 8 + i * 2 + half;   // global A row
            int n = r >> 10;                            // batch
            int t = r & 1023;                           // time
            float* C = g_xw + (size_t)(t * NB + n) * FH + bx * 128;
            float4 v0, v1;
            v0.x = (half ? acc[i][0].f.y : acc[i][0].f.x) + bb[0];
            v0.y = (half ? acc[i][1].f.y : acc[i][1].f.x) + bb[1];
            v0.z = (half ? acc[i][2].f.y : acc[i][2].f.x) + bb[2];
            v0.w = (half ? acc[i][3].f.y : acc[i][3].f.x) + bb[3];
            v1.x = (half ? acc[i][4].f.y : acc[i][4].f.x) + bb[4];
            v1.y = (half ? acc[i][5].f.y : acc[i][5].f.x) + bb[5];
            v1.z = (half ? acc[i][6].f.y : acc[i][6].f.x) + bb[6];
            v1.w = (half ? acc[i][7].f.y : acc[i][7].f.x) + bb[7];
            *(float4*)(C + tx * 8)     = v0;
            *(float4*)(C + tx * 8 + 4) = v1;
        }
    }
}

// ---------------------------------------------------------------------------
// Phase 2: ONE persistent kernel, tree grid barrier between timesteps.
// 128 blocks x 512 threads. Block b owns 4 hidden units (m0 = b*4) -> 16 cols.
// Whs2 [512 x 16] duplicated pairs (64 KB, loaded once).
// Hs   [512 x 68] h staging (136 KB), pre-transposed in g_hT. Ap ALIASES Hs.
// Barrier: red.release arrivals into 8 group counters; 8 masters promote to
// a root counter; ALL threads ld.acquire-poll the root, then fall straight
// into staging. No threadfence, no trailing syncthreads.
// ---------------------------------------------------------------------------
__global__ __launch_bounds__(NTHR) void lstm_persist_kernel(
    const float* __restrict__ Wh,     // [512, 2048]
    float* __restrict__ out)          // [64, 1024, 512]
{
    extern __shared__ char sm_raw[];
    float2* Whs2 = (float2*)sm_raw;                       // [512*16] pairs, 64KB
    float*  Hs   = (float*)(sm_raw + 65536);              // [512][68], 136KB
    float*  Ap   = Hs;                                    // aliased reduce buf

    const int tid  = threadIdx.x;
    const int w    = tid >> 5;
    const int lane = tid & 31;
    const int ln   = lane >> 2;   // 0..7  -> n group (8 batches)
    const int lc   = lane & 3;    // 0..3  -> c group (4 cols)
    const int m0   = blockIdx.x * 4;
    const int grp  = blockIdx.x >> 4;             // 0..7
    const bool master = ((blockIdx.x & 15) == 0);

    // Load Wh slice once, duplicated: col c = g*4+u -> global g*512 + m0 + u
    {
        const int wc  = tid & 15;
        const int wk0 = tid >> 4;       // 0..31
        const int wcol = (wc >> 2) * HH + m0 + (wc & 3);
        #pragma unroll 4
        for (int j = 0; j < 16; ++j) {
            int k = wk0 + 32 * j;
            float v = Wh[(size_t)k * FH + wcol];
            Whs2[k * 16 + wc] = make_float2(v, v);
        }
    }

    const int en = (tid >> 2) & 63;   // epilogue batch 0..63 (tid<256 active)
    const int eu = tid & 3;           // epilogue unit  0..3
    float creg = 0.f;

    // Staging map: thread -> row sk(+128j), float4 f = sq + 4m
    const int sk = tid >> 2;      // 0..127
    const int sq = tid & 3;       // 0..3

    // Prefetch xw for t = 0
    float xwv[4];
    #pragma unroll
    for (int g = 0; g < 4; ++g)
        xwv[g] = g_xw[(size_t)(0 * NB + en) * FH + g * HH + m0 + eu];

    for (int t = 0; t < TT; ++t) {
        const float* hp = g_hT[(t + 1) & 1];   // (t-1) mod 2; t=0 -> h0T in buf 1

        // Stage h_{t-1} -> Hs (already transposed in global; straight copy)
        #pragma unroll
        for (int j = 0; j < 4; ++j) {
            int row = sk + 128 * j;
            const float4* src = (const float4*)(hp + row * NB);
            float4* dst = (float4*)(Hs + row * HS_STRIDE);
            #pragma unroll
            for (int m = 0; m < 4; ++m) {
                int f = sq + 4 * m;
                dst[f] = __ldcg(src + f);
            }
        }
        __syncthreads();

        // Split-K: warp w owns k in [w*32, w*32+32). Lane tile 8n x 4c.
        F2 acc[4][4];
        #pragma unroll
        for (int p = 0; p < 4; ++p)
            #pragma unroll
            for (int j = 0; j < 4; ++j)
                acc[p][j].u = 0ull;

        #pragma unroll 4
        for (int kk = 0; kk < 32; ++kk) {
            int k = w * 32 + kk;
            const float* hrow = &Hs[k * HS_STRIDE];
            float4 ha = *(const float4*)&hrow[ln * 8];
            float4 hb = *(const float4*)&hrow[ln * 8 + 4];
            F2 hv[4];
            hv[0].f = make_float2(ha.x, ha.y);
            hv[1].f = make_float2(ha.z, ha.w);
            hv[2].f = make_float2(hb.x, hb.y);
            hv[3].f = make_float2(hb.z, hb.w);
            const float4* wp = (const float4*)&Whs2[k * 16 + lc * 4];
            float4 w0 = wp[0];                      // (c0,c0,c1,c1)
            float4 w1 = wp[1];                      // (c2,c2,c3,c3)
            F2 wv[4];
            wv[0].f = make_float2(w0.x, w0.y);
            wv[1].f = make_float2(w0.z, w0.w);
            wv[2].f = make_float2(w1.x, w1.y);
            wv[3].f = make_float2(w1.z, w1.w);
            #pragma unroll
            for (int j = 0; j < 4; ++j)
                #pragma unroll
                for (int p = 0; p < 4; ++p)
                    FMA2(acc[p][j], hv[p], wv[j]);
        }

        __syncthreads();   // all warps done READING Hs; safe to alias as Ap

        // Cross-warp partials (stride 66, float2 stores)
        #pragma unroll
        for (int p = 0; p < 4; ++p)
            #pragma unroll
            for (int j = 0; j < 4; ++j)
                *(float2*)&Ap[(w * 16 + lc * 4 + j) * 66 + ln * 8 + 2 * p] =
                    acc[p][j].f;
        __syncthreads();

        float hval = 0.f;
        if (tid < 256) {
            float a[4];
            #pragma unroll
            for (int g = 0; g < 4; ++g) {
                float s = xwv[g];
                #pragma unroll
                for (int ww = 0; ww < 16; ++ww)
                    s += Ap[(ww * 16 + g * 4 + eu) * 66 + en];
                a[g] = s;
            }
            float ig = sigmoid_fast(a[0]);
            float fg = sigmoid_fast(a[1]);
            float og = sigmoid_fast(a[2]);
            float gg = tanh_fast(a[3]);
            creg = fmaf(fg, creg, ig * gg);
            hval = og * tanh_fast(creg);
            // h for next step FIRST (it's what other blocks wait on)
            g_hT[t & 1][(m0 + eu) * NB + en] = hval;
        }

        if (t + 1 < TT) {
            __syncthreads();                 // block's h stores all issued
            if (tid == 0)
                red_release(&g_bar_grp[grp]);    // release-arrival (tree leaf)

            // ---- overlapped with the barrier: out store + next xw prefetch
            if (tid < 256) {
                out[(size_t)en * TT * HH + (size_t)t * HH + m0 + eu] = hval;
                #pragma unroll
                for (int g = 0; g < 4; ++g)
                    xwv[g] = g_xw[(size_t)((t + 1) * NB + en) * FH + g * HH + m0 + eu];
            }

            if (master && tid == 0) {
                const unsigned gt = 16u * (unsigned)(t + 1);
                while (ld_acquire(&g_bar_grp[grp]) < gt) { }
                red_release(&g_bar_root);        // promote group to root
            }
            const unsigned rt = (unsigned)(NGRP * (t + 1));
            while (ld_acquire(&g_bar_root) < rt) { }
            // fall straight into next staging (post-staging sync orders Hs)
        } else {
            if (tid < 256)
                out[(size_t)en * TT * HH + (size_t)t * HH + m0 + eu] = hval;
        }
    }
}

// ---------------------------------------------------------------------------
extern "C" void kernel_launch(void* const* d_in, const int* in_sizes, int n_in,
                              void* d_out, int out_size)
{
    const float* x  = (const float*)d_in[0];   // [64, 1024, 512]
    const float* h0 = (const float*)d_in[1];   // [64, 512]
    const float* Wx = (const float*)d_in[2];   // [512, 2048]
    const float* Wh = (const float*)d_in[3];   // [512, 2048]
    const float* b  = (const float*)d_in[4];   // [2048]
    float* out = (float*)d_out;                // [64, 1024, 512]

    const int smem_bytes = 65536 + DD * HS_STRIDE * 4;   // 64KB + 136KB = 200KB
    cudaFuncSetAttribute(lstm_persist_kernel,
                         cudaFuncAttributeMaxDynamicSharedMemorySize, smem_bytes);

    transpose_h0_kernel<<<128, 256>>>(h0);

    dim3 g1(FH / 128, (NB * TT) / 128);        // (16, 512)
    sgemm_xw_kernel<<<g1, 256>>>(x, Wx, b);

    lstm_persist_kernel<<<GRID_R, NTHR, smem_bytes>>>(Wh, out);
}

// round 10
// speedup vs baseline: 1.2534x; 1.2534x over previous
#include <cuda_runtime.h>
#include <math.h>

#define NB 64
#define TT 1024
#define DD 512
#define HH 512
#define FH 2048     // 4*H
#define GGRP 4      // independent batch groups
#define BPG 32      // blocks per group
#define NBG 16      // batches per group
#define GRID_R (GGRP * BPG)   // 128 blocks, 1/SM
#define NTHR 512
#define HS2_STRIDE 34         // float2 units per kp row (16 data + 2 pad; 272B)

// xw in [T, N, 4H] layout (512 MB); per-group transposed ping-pong h; barriers.
__device__ float g_xw[(size_t)NB * TT * FH];
__device__ float g_hT[2][GGRP][DD][NBG];    // [buf][grp][k][n]  h transposed
__device__ unsigned g_cnt[GGRP * 32];       // arrival counters (128B apart)
__device__ unsigned g_rel[GGRP * 32];       // release flags (separate lines)

union F2 { float2 f; unsigned long long u; };

#define FMA2(d, a, b) \
    asm("fma.rn.f32x2 %0, %1, %2, %3;" : "=l"((d).u) : "l"((a).u), "l"((b).u), "l"((d).u))

__device__ __forceinline__ float tanh_fast(float x) {
    float y;
    asm("tanh.approx.f32 %0, %1;" : "=f"(y) : "f"(x));
    return y;
}
__device__ __forceinline__ float sigmoid_fast(float x) {
    return fmaf(tanh_fast(0.5f * x), 0.5f, 0.5f);
}

__device__ __forceinline__ unsigned ld_acquire(const unsigned* p) {
    unsigned v;
    asm volatile("ld.acquire.gpu.global.u32 %0, [%1];" : "=r"(v) : "l"(p) : "memory");
    return v;
}

// ---------------------------------------------------------------------------
// Phase 1: xw[t*64+n, j] = sum_k x[n*1024+t, k] * Wx[k, j] + b[j]
// fp32 SGEMM, packed f32x2 FMA: BM=128, BN=128, BK=8, 256 thr, 8x8/thr.
// ---------------------------------------------------------------------------
__global__ __launch_bounds__(256) void sgemm_xw_kernel(
    const float* __restrict__ A,      // x    [65536, 512]
    const float* __restrict__ B,      // Wx   [512, 2048]
    const float* __restrict__ bias)   // b    [2048]
{
    __shared__ float As[8][128];
    __shared__ float Bs2[8][256];     // duplicated pairs (v, v)

    const int tid = threadIdx.x;
    const int bx = blockIdx.x;
    const int by = blockIdx.y;
    const int tx = tid & 15;
    const int ty = tid >> 4;

    if (bx == 0 && by == 0 && tid < GGRP) {   // reset phase-2 barriers
        g_cnt[tid * 32] = 0u;
        g_rel[tid * 32] = 0u;
    }

    const float* Ab = A + (size_t)by * 128 * DD;
    const float* Bb = B + bx * 128;

    F2 acc[4][8];
    #pragma unroll
    for (int i = 0; i < 4; ++i)
        #pragma unroll
        for (int j = 0; j < 8; ++j)
            acc[i][j].u = 0ull;

    const int arow = tid >> 1;
    const int ac4  = (tid & 1) * 4;
    const int brow = tid >> 5;
    const int bc4  = (tid & 31) * 4;

    for (int kc = 0; kc < DD; kc += 8) {
        float4 av = *(const float4*)(Ab + (size_t)arow * DD + kc + ac4);
        float4 bv = *(const float4*)(Bb + (size_t)(kc + brow) * FH + bc4);
        As[ac4 + 0][arow] = av.x;
        As[ac4 + 1][arow] = av.y;
        As[ac4 + 2][arow] = av.z;
        As[ac4 + 3][arow] = av.w;
        *(float2*)&Bs2[brow][2 * (bc4 + 0)] = make_float2(bv.x, bv.x);
        *(float2*)&Bs2[brow][2 * (bc4 + 1)] = make_float2(bv.y, bv.y);
        *(float2*)&Bs2[brow][2 * (bc4 + 2)] = make_float2(bv.z, bv.z);
        *(float2*)&Bs2[brow][2 * (bc4 + 3)] = make_float2(bv.w, bv.w);
        __syncthreads();

        #pragma unroll
        for (int k = 0; k < 8; ++k) {
            float4 a0 = *(const float4*)&As[k][ty * 8];
            float4 a1 = *(const float4*)&As[k][ty * 8 + 4];
            F2 ra[4];
            ra[0].f = make_float2(a0.x, a0.y);
            ra[1].f = make_float2(a0.z, a0.w);
            ra[2].f = make_float2(a1.x, a1.y);
            ra[3].f = make_float2(a1.z, a1.w);
            #pragma unroll
            for (int j = 0; j < 8; ++j) {
                F2 rb = *(F2*)&Bs2[k][2 * (tx * 8 + j)];
                #pragma unroll
                for (int i = 0; i < 4; ++i)
                    FMA2(acc[i][j], ra[i], rb);
            }
        }
        __syncthreads();
    }

    float bb[8];
    #pragma unroll
    for (int j = 0; j < 8; ++j)
        bb[j] = bias[bx * 128 + tx * 8 + j];

    #pragma unroll
    for (int i = 0; i < 4; ++i) {
        #pragma unroll
        for (int half = 0; half < 2; ++half) {
            int r = by * 128 + ty * 8 + i * 2 + half;
            int n = r >> 10;
            int t = r & 1023;
            float* C = g_xw + (size_t)(t * NB + n) * FH + bx * 128;
            float4 v0, v1;
            v0.x = (half ? acc[i][0].f.y : acc[i][0].f.x) + bb[0];
            v0.y = (half ? acc[i][1].f.y : acc[i][1].f.x) + bb[1];
            v0.z = (half ? acc[i][2].f.y : acc[i][2].f.x) + bb[2];
            v0.w = (half ? acc[i][3].f.y : acc[i][3].f.x) + bb[3];
            v1.x = (half ? acc[i][4].f.y : acc[i][4].f.x) + bb[4];
            v1.y = (half ? acc[i][5].f.y : acc[i][5].f.x) + bb[5];
            v1.z = (half ? acc[i][6].f.y : acc[i][6].f.x) + bb[6];
            v1.w = (half ? acc[i][7].f.y : acc[i][7].f.x) + bb[7];
            *(float4*)(C + tx * 8)     = v0;
            *(float4*)(C + tx * 8 + 4) = v1;
        }
    }
}

// ---------------------------------------------------------------------------
// Phase 2: persistent kernel; 4 INDEPENDENT groups x 32 blocks.
// Group g owns batches [16g, 16g+16). Block (rank r in group) owns 16 hidden
// units u in [16r, 16r+16) -> 64 gate columns (g4*512 + 16r + u).
// Wh slice lives in REGISTERS: thread (col ct, kslice ks) holds wv[32] f32x2
// k-pairs of its column. GEMM: acc[n].x/.y accumulate even/odd k; h operand
// is a 128B broadcast row per k-pair (no duplication, ~no smem BW).
// Per-group barrier: 32 acq_rel arrivals -> last writes release flag (its own
// line); tid0 polls; out-store + xw prefetch overlap the spin.
// Dyn smem: Hs2 [256 kp][34 f2] = 68KB, Ap [8][16][64] = 32KB -> 100KB.
// ---------------------------------------------------------------------------
__global__ __launch_bounds__(NTHR, 1) void lstm_persist_kernel(
    const float* __restrict__ Wh,     // [512, 2048]
    const float* __restrict__ h0,     // [64, 512]
    float* __restrict__ out)          // [64, 1024, 512]
{
    extern __shared__ char sm_raw[];
    float2* Hs2 = (float2*)sm_raw;                               // [256][34]
    float*  Ap  = (float*)(sm_raw + 256 * HS2_STRIDE * 8);       // [8][16][64]

    const int tid  = threadIdx.x;
    const int grp  = blockIdx.x >> 5;     // 0..3
    const int rank = blockIdx.x & 31;     // 0..31

    // GEMM thread mapping
    const int ct = tid & 63;              // local col 0..63
    const int ks = tid >> 6;              // k-slice 0..7 (64 k each)
    const int gcol = (ct >> 4) * HH + 16 * rank + (ct & 15);

    // Load Wh slice into registers ONCE: wv[j] = (Wh[k0+2j][gcol], Wh[k0+2j+1][gcol])
    F2 wv[32];
    {
        const float* wp = Wh + (size_t)(ks * 64) * FH + gcol;
        #pragma unroll
        for (int j = 0; j < 32; ++j) {
            wv[j].f.x = wp[(size_t)(2 * j) * FH];
            wv[j].f.y = wp[(size_t)(2 * j + 1) * FH];
        }
    }

    // Staging map: thread -> (kp row, half of 8 n)
    const int skp  = tid >> 1;            // 0..255
    const int shalf = tid & 1;            // 0..1

    // Epilogue map: 2 threads per (n, u) item
    const int item = tid >> 1;            // 0..255
    const int kh   = tid & 1;
    const int en   = item >> 4;           // local batch 0..15
    const int eu   = item & 15;           // local unit 0..15
    const int ng   = NBG * grp + en;      // global batch
    const int ug   = 16 * rank + eu;      // global unit
    float creg = 0.f;                     // cell state (kh==0 threads)

    unsigned* cnt = &g_cnt[grp * 32];
    unsigned* rel = &g_rel[grp * 32];

    // Prefetch xw for t = 0
    float xwv[4];
    if (kh == 0) {
        #pragma unroll
        for (int g = 0; g < 4; ++g)
            xwv[g] = g_xw[(size_t)(0 * NB + ng) * FH + g * HH + ug];
    }

    for (int t = 0; t < TT; ++t) {
        // ---- Stage h_{t-1} -> Hs2[kp][n] = (h[2kp][n], h[2kp+1][n]) ----
        if (t == 0) {
            // from h0 [n][512]: k-pairs are consecutive -> float2 loads
            #pragma unroll
            for (int i = 0; i < 8; ++i) {
                int n = shalf * 8 + i;
                float2 v = *(const float2*)(h0 + (size_t)(NBG * grp + n) * DD + 2 * skp);
                Hs2[skp * HS2_STRIDE + shalf * 8 + i] = v;
            }
        } else {
            const float* src = &g_hT[(t + 1) & 1][grp][0][0];
            const float4* s0 = (const float4*)(src + (2 * skp) * NBG + shalf * 8);
            const float4* s1 = (const float4*)(src + (2 * skp + 1) * NBG + shalf * 8);
            float4 e0 = __ldcg(s0), e1 = __ldcg(s0 + 1);
            float4 o0 = __ldcg(s1), o1 = __ldcg(s1 + 1);
            float4* d4 = (float4*)(Hs2 + skp * HS2_STRIDE + shalf * 8);
            d4[0] = make_float4(e0.x, o0.x, e0.y, o0.y);
            d4[1] = make_float4(e0.z, o0.z, e0.w, o0.w);
            d4[2] = make_float4(e1.x, o1.x, e1.y, o1.y);
            d4[3] = make_float4(e1.z, o1.z, e1.w, o1.w);
        }
        __syncthreads();

        // ---- GEMM: thread = 1 col x 16 n x 32 k-pairs (Wh in regs) ----
        F2 acc[16];
        #pragma unroll
        for (int n = 0; n < 16; ++n)
            acc[n].u = 0ull;

        const float2* hb = Hs2 + (size_t)(ks * 32) * HS2_STRIDE;
        #pragma unroll
        for (int j = 0; j < 32; ++j) {
            const float4* hr = (const float4*)(hb + j * HS2_STRIDE);
            #pragma unroll
            for (int q = 0; q < 8; ++q) {
                float4 hq = hr[q];            // n=2q and n=2q+1 (even,odd k)
                F2 lo, hi;
                lo.f = make_float2(hq.x, hq.y);
                hi.f = make_float2(hq.z, hq.w);
                FMA2(acc[2 * q],     lo, wv[j]);
                FMA2(acc[2 * q + 1], hi, wv[j]);
            }
        }

        // ---- partials to smem: Ap[ks][n][ct] ----
        #pragma unroll
        for (int n = 0; n < 16; ++n)
            Ap[(ks * 16 + n) * 64 + ct] = acc[n].f.x + acc[n].f.y;
        __syncthreads();

        // ---- reduce (2 threads/item over 8 k-slices) + gates ----
        float a[4];
        #pragma unroll
        for (int g = 0; g < 4; ++g) {
            float s = 0.f;
            #pragma unroll
            for (int k2 = 0; k2 < 4; ++k2)
                s += Ap[((kh * 4 + k2) * 16 + en) * 64 + g * 16 + eu];
            s += __shfl_xor_sync(0xFFFFFFFFu, s, 1);
            a[g] = s;
        }

        float hval = 0.f;
        if (kh == 0) {
            float ig = sigmoid_fast(a[0] + xwv[0]);
            float fg = sigmoid_fast(a[1] + xwv[1]);
            float og = sigmoid_fast(a[2] + xwv[2]);
            float gg = tanh_fast(a[3] + xwv[3]);
            creg = fmaf(fg, creg, ig * gg);
            hval = og * tanh_fast(creg);
            g_hT[t & 1][grp][ug][en] = hval;   // h for next step first
        }

        if (t + 1 < TT) {
            __syncthreads();                   // all h stores issued block-wide
            if (tid == 0) {
                unsigned old;
                asm volatile("atom.acq_rel.gpu.global.add.u32 %0, [%1], 1;"
                             : "=r"(old) : "l"(cnt) : "memory");
                if (old == (unsigned)(BPG * (t + 1)) - 1u) {
                    unsigned v = (unsigned)(t + 1);
                    asm volatile("st.release.gpu.global.u32 [%0], %1;"
                                 :: "l"(rel), "r"(v) : "memory");
                }
            }
            // ---- overlapped with the spin: out store + next xw prefetch ----
            if (kh == 0) {
                out[(size_t)ng * TT * HH + (size_t)t * HH + ug] = hval;
                #pragma unroll
                for (int g = 0; g < 4; ++g)
                    xwv[g] = g_xw[(size_t)((t + 1) * NB + ng) * FH + g * HH + ug];
            }
            if (tid == 0) {
                while (ld_acquire(rel) < (unsigned)(t + 1)) { }
            }
            __syncthreads();
        } else {
            if (kh == 0)
                out[(size_t)ng * TT * HH + (size_t)t * HH + ug] = hval;
        }
    }
}

// ---------------------------------------------------------------------------
extern "C" void kernel_launch(void* const* d_in, const int* in_sizes, int n_in,
                              void* d_out, int out_size)
{
    const float* x  = (const float*)d_in[0];   // [64, 1024, 512]
    const float* h0 = (const float*)d_in[1];   // [64, 512]
    const float* Wx = (const float*)d_in[2];   // [512, 2048]
    const float* Wh = (const float*)d_in[3];   // [512, 2048]
    const float* b  = (const float*)d_in[4];   // [2048]
    float* out = (float*)d_out;                // [64, 1024, 512]

    const int smem_bytes = 256 * HS2_STRIDE * 8 + 8 * 16 * 64 * 4;  // 68KB+32KB
    cudaFuncSetAttribute(lstm_persist_kernel,
                         cudaFuncAttributeMaxDynamicSharedMemorySize, smem_bytes);

    dim3 g1(FH / 128, (NB * TT) / 128);        // (16, 512)
    sgemm_xw_kernel<<<g1, 256>>>(x, Wx, b);

    lstm_persist_kernel<<<GRID_R, NTHR, smem_bytes>>>(Wh, h0, out);
}

// round 11
// speedup vs baseline: 1.3135x; 1.0479x over previous
#include <cuda_runtime.h>
#include <math.h>

#define NB 64
#define TT 1024
#define DD 512
#define HH 512
#define FH 2048     // 4*H
#define GGRP 4      // independent batch groups
#define BPG 32      // blocks per group
#define NBG 16      // batches per group
#define GRID_R (GGRP * BPG)   // 128 blocks, 1/SM
#define NTHR 512
#define NQ 4        // k-quarters (sub-barriers) per group

// xw in [T, N, 4H] layout (512 MB); paired-layout ping-pong h; sub-barriers.
__device__ float g_xw[(size_t)NB * TT * FH];
// g_h2[buf][grp][kp][n*2 + parity] : (h[2kp][n], h[2kp+1][n]) pairs, 32 floats/row
__device__ float g_h2[2][GGRP][DD / 2][2 * NBG];
__device__ unsigned g_cnt[GGRP * NQ * 32];   // counters, 128B apart

union F2 { float2 f; unsigned long long u; };

#define FMA2(d, a, b) \
    asm("fma.rn.f32x2 %0, %1, %2, %3;" : "=l"((d).u) : "l"((a).u), "l"((b).u), "l"((d).u))

__device__ __forceinline__ float tanh_fast(float x) {
    float y;
    asm("tanh.approx.f32 %0, %1;" : "=f"(y) : "f"(x));
    return y;
}
__device__ __forceinline__ float sigmoid_fast(float x) {
    return fmaf(tanh_fast(0.5f * x), 0.5f, 0.5f);
}
__device__ __forceinline__ unsigned ld_acquire(const unsigned* p) {
    unsigned v;
    asm volatile("ld.acquire.gpu.global.u32 %0, [%1];" : "=r"(v) : "l"(p) : "memory");
    return v;
}
__device__ __forceinline__ void atom_release_add(unsigned* p) {
    unsigned old;
    asm volatile("atom.release.gpu.global.add.u32 %0, [%1], 1;"
                 : "=r"(old) : "l"(p) : "memory");
}

// ---------------------------------------------------------------------------
// Phase 1: xw[t*64+n, j] = sum_k x[n*1024+t, k] * Wx[k, j] + b[j]
// fp32 SGEMM, packed f32x2 FMA: BM=128, BN=128, BK=8, 256 thr, 8x8/thr.
// ---------------------------------------------------------------------------
__global__ __launch_bounds__(256) void sgemm_xw_kernel(
    const float* __restrict__ A,      // x    [65536, 512]
    const float* __restrict__ B,      // Wx   [512, 2048]
    const float* __restrict__ bias)   // b    [2048]
{
    __shared__ float As[8][128];
    __shared__ float Bs2[8][256];     // duplicated pairs (v, v)

    const int tid = threadIdx.x;
    const int bx = blockIdx.x;
    const int by = blockIdx.y;
    const int tx = tid & 15;
    const int ty = tid >> 4;

    if (bx == 0 && by == 0 && tid < GGRP * NQ)   // reset phase-2 sub-barriers
        g_cnt[tid * 32] = 0u;

    const float* Ab = A + (size_t)by * 128 * DD;
    const float* Bb = B + bx * 128;

    F2 acc[4][8];
    #pragma unroll
    for (int i = 0; i < 4; ++i)
        #pragma unroll
        for (int j = 0; j < 8; ++j)
            acc[i][j].u = 0ull;

    const int arow = tid >> 1;
    const int ac4  = (tid & 1) * 4;
    const int brow = tid >> 5;
    const int bc4  = (tid & 31) * 4;

    for (int kc = 0; kc < DD; kc += 8) {
        float4 av = *(const float4*)(Ab + (size_t)arow * DD + kc + ac4);
        float4 bv = *(const float4*)(Bb + (size_t)(kc + brow) * FH + bc4);
        As[ac4 + 0][arow] = av.x;
        As[ac4 + 1][arow] = av.y;
        As[ac4 + 2][arow] = av.z;
        As[ac4 + 3][arow] = av.w;
        *(float2*)&Bs2[brow][2 * (bc4 + 0)] = make_float2(bv.x, bv.x);
        *(float2*)&Bs2[brow][2 * (bc4 + 1)] = make_float2(bv.y, bv.y);
        *(float2*)&Bs2[brow][2 * (bc4 + 2)] = make_float2(bv.z, bv.z);
        *(float2*)&Bs2[brow][2 * (bc4 + 3)] = make_float2(bv.w, bv.w);
        __syncthreads();

        #pragma unroll
        for (int k = 0; k < 8; ++k) {
            float4 a0 = *(const float4*)&As[k][ty * 8];
            float4 a1 = *(const float4*)&As[k][ty * 8 + 4];
            F2 ra[4];
            ra[0].f = make_float2(a0.x, a0.y);
            ra[1].f = make_float2(a0.z, a0.w);
            ra[2].f = make_float2(a1.x, a1.y);
            ra[3].f = make_float2(a1.z, a1.w);
            #pragma unroll
            for (int j = 0; j < 8; ++j) {
                F2 rb = *(F2*)&Bs2[k][2 * (tx * 8 + j)];
                #pragma unroll
                for (int i = 0; i < 4; ++i)
                    FMA2(acc[i][j], ra[i], rb);
            }
        }
        __syncthreads();
    }

    float bb[8];
    #pragma unroll
    for (int j = 0; j < 8; ++j)
        bb[j] = bias[bx * 128 + tx * 8 + j];

    #pragma unroll
    for (int i = 0; i < 4; ++i) {
        #pragma unroll
        for (int half = 0; half < 2; ++half) {
            int r = by * 128 + ty * 8 + i * 2 + half;
            int n = r >> 10;
            int t = r & 1023;
            float* C = g_xw + (size_t)(t * NB + n) * FH + bx * 128;
            float4 v0, v1;
            v0.x = (half ? acc[i][0].f.y : acc[i][0].f.x) + bb[0];
            v0.y = (half ? acc[i][1].f.y : acc[i][1].f.x) + bb[1];
            v0.z = (half ? acc[i][2].f.y : acc[i][2].f.x) + bb[2];
            v0.w = (half ? acc[i][3].f.y : acc[i][3].f.x) + bb[3];
            v1.x = (half ? acc[i][4].f.y : acc[i][4].f.x) + bb[4];
            v1.y = (half ? acc[i][5].f.y : acc[i][5].f.x) + bb[5];
            v1.z = (half ? acc[i][6].f.y : acc[i][6].f.x) + bb[6];
            v1.w = (half ? acc[i][7].f.y : acc[i][7].f.x) + bb[7];
            *(float4*)(C + tx * 8)     = v0;
            *(float4*)(C + tx * 8 + 4) = v1;
        }
    }
}

// ---------------------------------------------------------------------------
// Phase 2: persistent kernel; 4 independent groups x 32 blocks.
// Sub-barrier pipelining: quarter q of the k-range (k in [128q, 128q+128))
// is produced by blocks rank 8q..8q+7 and gets its own 8-arrival counter.
// Consumer warp w needs only quarter w>>2: lane0-polls it, stages its own
// 2KB h slice (contiguous, XOR-granule swizzled into smem), named-bars with
// its ks-partner warp, then runs its GEMM. Quarters 1-3's latency hides
// under quarters 0-2's compute; per-block skew is absorbed, not amplified.
// Wh lives in registers (32 f32x2/thread). Smem: Hs 32KB + Ap 32KB.
// ---------------------------------------------------------------------------
__global__ __launch_bounds__(NTHR, 1) void lstm_persist_kernel(
    const float* __restrict__ Wh,     // [512, 2048]
    const float* __restrict__ h0,     // [64, 512]
    float* __restrict__ out)          // [64, 1024, 512]
{
    extern __shared__ char sm_raw[];
    float* Hs = (float*)sm_raw;                       // [256 kp][32] swizzled
    float* Ap = (float*)(sm_raw + 256 * 32 * 4);      // [8][16][64]

    const int tid  = threadIdx.x;
    const int lane = tid & 31;
    const int wrp  = tid >> 5;            // 0..15
    const int grp  = blockIdx.x >> 5;     // 0..3
    const int rank = blockIdx.x & 31;     // 0..31

    // GEMM thread mapping: ks = k-slice (64 k), ct = local gate column
    const int ct = tid & 63;              // 0..63
    const int ks = tid >> 6;              // 0..7
    const int qw = wrp >> 2;              // quarter this warp consumes
    const int gcol = (ct >> 4) * HH + 16 * rank + (ct & 15);

    // Wh slice in registers: wv[j] = (Wh[k0+2j][gcol], Wh[k0+2j+1][gcol])
    F2 wv[32];
    {
        const float* wp = Wh + (size_t)(ks * 64) * FH + gcol;
        #pragma unroll
        for (int j = 0; j < 32; ++j) {
            wv[j].f.x = wp[(size_t)(2 * j) * FH];
            wv[j].f.y = wp[(size_t)(2 * j + 1) * FH];
        }
    }

    // Staging map: warp stages 16 rows of its ks range; lane pair per row.
    const int srow0 = ks * 32 + (wrp & 1) * 16;   // first kp row this warp stages
    const int srow  = srow0 + (lane >> 1);        // this lane's kp row
    const int shalf = lane & 1;                   // which 64B half of the row

    // Epilogue map: 2 threads per (n, u) item
    const int item = tid >> 1;
    const int kh   = tid & 1;
    const int en   = item >> 4;           // local batch 0..15
    const int eu   = item & 15;           // local unit 0..15
    const int ng   = NBG * grp + en;
    const int ug   = 16 * rank + eu;
    float creg = 0.f;

    unsigned* cnt_mine = &g_cnt[(grp * NQ + (rank >> 3)) * 32];  // arrive here
    unsigned* cnt_need = &g_cnt[(grp * NQ + qw) * 32];           // poll this

    // Prefetch xw for t = 0
    float xwv[4];
    if (kh == 0) {
        #pragma unroll
        for (int g = 0; g < 4; ++g)
            xwv[g] = g_xw[(size_t)(0 * NB + ng) * FH + g * HH + ug];
    }

    for (int t = 0; t < TT; ++t) {
        // ---- per-warp: wait for my quarter, stage my 2KB, pair-sync ----
        if (t > 0) {
            if (lane == 0) {
                const unsigned tgt = 8u * (unsigned)t;
                while (ld_acquire(cnt_need) < tgt) { }
            }
            __syncwarp();
            // Stage: row srow (32 floats = 8 granules), this lane's half
            const float* src = &g_h2[(t + 1) & 1][grp][srow][shalf * 16];
            float* dstrow = Hs + srow * 32;
            const int sw = srow & 7;
            #pragma unroll
            for (int m = 0; m < 4; ++m) {
                int g = shalf * 4 + m;
                float4 v = __ldcg((const float4*)(src + m * 4));
                *(float4*)(dstrow + ((g ^ sw) * 4)) = v;
            }
        } else {
            // t == 0: gather h0 pairs into the swizzled layout
            const int sw = srow & 7;
            float* dstrow = Hs + srow * 32;
            #pragma unroll
            for (int ln = 0; ln < 8; ++ln) {
                int n = shalf * 8 + ln;
                float2 v = *(const float2*)(h0 + (size_t)(NBG * grp + n) * DD + 2 * srow);
                int g = shalf * 4 + (ln >> 1);
                *(float2*)(dstrow + ((g ^ sw) * 4) + (ln & 1) * 2) = v;
            }
        }
        asm volatile("bar.sync %0, 64;" :: "r"(1 + ks) : "memory");

        // ---- GEMM: 1 col x 16 n x 32 k-pairs, Wh in regs ----
        F2 acc[16];
        #pragma unroll
        for (int n = 0; n < 16; ++n)
            acc[n].u = 0ull;

        #pragma unroll
        for (int j = 0; j < 32; ++j) {
            const int row = ks * 32 + j;
            const float* hrow = Hs + row * 32;
            const int sw = row & 7;
            #pragma unroll
            for (int q = 0; q < 8; ++q) {
                float4 hq = *(const float4*)(hrow + ((q ^ sw) * 4));
                F2 lo, hi;
                lo.f = make_float2(hq.x, hq.y);   // n=2q   (even k, odd k)
                hi.f = make_float2(hq.z, hq.w);   // n=2q+1
                FMA2(acc[2 * q],     lo, wv[j]);
                FMA2(acc[2 * q + 1], hi, wv[j]);
            }
        }

        // ---- partials ----
        #pragma unroll
        for (int n = 0; n < 16; ++n)
            Ap[(ks * 16 + n) * 64 + ct] = acc[n].f.x + acc[n].f.y;
        __syncthreads();

        // ---- reduce (2 threads/item over 8 k-slices) + gates ----
        float a[4];
        #pragma unroll
        for (int g = 0; g < 4; ++g) {
            float s = 0.f;
            #pragma unroll
            for (int k2 = 0; k2 < 4; ++k2)
                s += Ap[((kh * 4 + k2) * 16 + en) * 64 + g * 16 + eu];
            s += __shfl_xor_sync(0xFFFFFFFFu, s, 1);
            a[g] = s;
        }

        float hval = 0.f;
        if (kh == 0) {
            float ig = sigmoid_fast(a[0] + xwv[0]);
            float fg = sigmoid_fast(a[1] + xwv[1]);
            float og = sigmoid_fast(a[2] + xwv[2]);
            float gg = tanh_fast(a[3] + xwv[3]);
            creg = fmaf(fg, creg, ig * gg);
            hval = og * tanh_fast(creg);
            // paired layout: row = ug>>1, word = en*2 + (ug&1)
            g_h2[t & 1][grp][ug >> 1][en * 2 + (ug & 1)] = hval;
        }
        __syncthreads();    // Ap reuse safety + all h stores before arrive

        if (t + 1 < TT) {
            if (tid == 0)
                atom_release_add(cnt_mine);
            // ---- overlapped with other blocks' progress ----
            if (kh == 0) {
                out[(size_t)ng * TT * HH + (size_t)t * HH + ug] = hval;
                #pragma unroll
                for (int g = 0; g < 4; ++g)
                    xwv[g] = g_xw[(size_t)((t + 1) * NB + ng) * FH + g * HH + ug];
            }
        } else {
            if (kh == 0)
                out[(size_t)ng * TT * HH + (size_t)t * HH + ug] = hval;
        }
    }
}

// ---------------------------------------------------------------------------
extern "C" void kernel_launch(void* const* d_in, const int* in_sizes, int n_in,
                              void* d_out, int out_size)
{
    const float* x  = (const float*)d_in[0];   // [64, 1024, 512]
    const float* h0 = (const float*)d_in[1];   // [64, 512]
    const float* Wx = (const float*)d_in[2];   // [512, 2048]
    const float* Wh = (const float*)d_in[3];   // [512, 2048]
    const float* b  = (const float*)d_in[4];   // [2048]
    float* out = (float*)d_out;                // [64, 1024, 512]

    const int smem_bytes = 256 * 32 * 4 + 8 * 16 * 64 * 4;  // 32KB + 32KB
    cudaFuncSetAttribute(lstm_persist_kernel,
                         cudaFuncAttributeMaxDynamicSharedMemorySize, smem_bytes);

    dim3 g1(FH / 128, (NB * TT) / 128);        // (16, 512)
    sgemm_xw_kernel<<<g1, 256>>>(x, Wx, b);

    lstm_persist_kernel<<<GRID_R, NTHR, smem_bytes>>>(Wh, h0, out);
}

// round 14
// speedup vs baseline: 1.3431x; 1.0225x over previous
#include <cuda_runtime.h>
#include <math.h>

#define NB 64
#define TT 1024
#define DD 512
#define HH 512
#define FH 2048     // 4*H
#define GGRP 4      // independent batch groups
#define BPG 32      // blocks per group
#define NBG 16      // batches per group
#define GRID_R (GGRP * BPG)   // 128 blocks, 1/SM
#define NTHR 512
#define NQ 4        // k-quarters (sub-barriers) per group

// xw in [T, N, 4H] layout (512 MB); paired-layout ping-pong h; sub-barriers.
__device__ float g_xw[(size_t)NB * TT * FH];
// g_h2[buf][grp][kp][n*2 + parity] : (h[2kp][n], h[2kp+1][n]) pairs, 32 floats/row
__device__ float g_h2[2][GGRP][DD / 2][2 * NBG];
__device__ unsigned g_cnt[GGRP * NQ * 32];   // counters, 128B apart

union F2 { float2 f; unsigned long long u; };

#define FMA2(d, a, b) \
    asm("fma.rn.f32x2 %0, %1, %2, %3;" : "=l"((d).u) : "l"((a).u), "l"((b).u), "l"((d).u))

__device__ __forceinline__ float tanh_fast(float x) {
    float y;
    asm("tanh.approx.f32 %0, %1;" : "=f"(y) : "f"(x));
    return y;
}
__device__ __forceinline__ float sigmoid_fast(float x) {
    return fmaf(tanh_fast(0.5f * x), 0.5f, 0.5f);
}
__device__ __forceinline__ unsigned ld_acquire(const unsigned* p) {
    unsigned v;
    asm volatile("ld.acquire.gpu.global.u32 %0, [%1];" : "=r"(v) : "l"(p) : "memory");
    return v;
}
__device__ __forceinline__ void atom_release_add(unsigned* p) {
    unsigned old;
    asm volatile("atom.release.gpu.global.add.u32 %0, [%1], 1;"
                 : "=r"(old) : "l"(p) : "memory");
}

// ---------------------------------------------------------------------------
// Phase 1: xw[t*64+n, j] = sum_k x[n*1024+t, k] * Wx[k, j] + b[j]
// fp32 SGEMM, packed f32x2 FMA: BM=128, BN=128, BK=8, 256 thr, 8x8/thr.
// ---------------------------------------------------------------------------
__global__ __launch_bounds__(256) void sgemm_xw_kernel(
    const float* __restrict__ A,      // x    [65536, 512]
    const float* __restrict__ B,      // Wx   [512, 2048]
    const float* __restrict__ bias)   // b    [2048]
{
    __shared__ float As[8][128];
    __shared__ float Bs2[8][256];     // duplicated pairs (v, v)

    const int tid = threadIdx.x;
    const int bx = blockIdx.x;
    const int by = blockIdx.y;
    const int tx = tid & 15;
    const int ty = tid >> 4;

    if (bx == 0 && by == 0 && tid < GGRP * NQ)   // reset phase-2 sub-barriers
        g_cnt[tid * 32] = 0u;

    const float* Ab = A + (size_t)by * 128 * DD;
    const float* Bb = B + bx * 128;

    F2 acc[4][8];
    #pragma unroll
    for (int i = 0; i < 4; ++i)
        #pragma unroll
        for (int j = 0; j < 8; ++j)
            acc[i][j].u = 0ull;

    const int arow = tid >> 1;
    const int ac4  = (tid & 1) * 4;
    const int brow = tid >> 5;
    const int bc4  = (tid & 31) * 4;

    for (int kc = 0; kc < DD; kc += 8) {
        float4 av = *(const float4*)(Ab + (size_t)arow * DD + kc + ac4);
        float4 bv = *(const float4*)(Bb + (size_t)(kc + brow) * FH + bc4);
        As[ac4 + 0][arow] = av.x;
        As[ac4 + 1][arow] = av.y;
        As[ac4 + 2][arow] = av.z;
        As[ac4 + 3][arow] = av.w;
        *(float2*)&Bs2[brow][2 * (bc4 + 0)] = make_float2(bv.x, bv.x);
        *(float2*)&Bs2[brow][2 * (bc4 + 1)] = make_float2(bv.y, bv.y);
        *(float2*)&Bs2[brow][2 * (bc4 + 2)] = make_float2(bv.z, bv.z);
        *(float2*)&Bs2[brow][2 * (bc4 + 3)] = make_float2(bv.w, bv.w);
        __syncthreads();

        #pragma unroll
        for (int k = 0; k < 8; ++k) {
            float4 a0 = *(const float4*)&As[k][ty * 8];
            float4 a1 = *(const float4*)&As[k][ty * 8 + 4];
            F2 ra[4];
            ra[0].f = make_float2(a0.x, a0.y);
            ra[1].f = make_float2(a0.z, a0.w);
            ra[2].f = make_float2(a1.x, a1.y);
            ra[3].f = make_float2(a1.z, a1.w);
            #pragma unroll
            for (int j = 0; j < 8; ++j) {
                F2 rb = *(F2*)&Bs2[k][2 * (tx * 8 + j)];
                #pragma unroll
                for (int i = 0; i < 4; ++i)
                    FMA2(acc[i][j], ra[i], rb);
            }
        }
        __syncthreads();
    }

    float bb[8];
    #pragma unroll
    for (int j = 0; j < 8; ++j)
        bb[j] = bias[bx * 128 + tx * 8 + j];

    #pragma unroll
    for (int i = 0; i < 4; ++i) {
        #pragma unroll
        for (int half = 0; half < 2; ++half) {
            int r = by * 128 + ty * 8 + i * 2 + half;
            int n = r >> 10;
            int t = r & 1023;
            float* C = g_xw + (size_t)(t * NB + n) * FH + bx * 128;
            float4 v0, v1;
            v0.x = (half ? acc[i][0].f.y : acc[i][0].f.x) + bb[0];
            v0.y = (half ? acc[i][1].f.y : acc[i][1].f.x) + bb[1];
            v0.z = (half ? acc[i][2].f.y : acc[i][2].f.x) + bb[2];
            v0.w = (half ? acc[i][3].f.y : acc[i][3].f.x) + bb[3];
            v1.x = (half ? acc[i][4].f.y : acc[i][4].f.x) + bb[4];
            v1.y = (half ? acc[i][5].f.y : acc[i][5].f.x) + bb[5];
            v1.z = (half ? acc[i][6].f.y : acc[i][6].f.x) + bb[6];
            v1.w = (half ? acc[i][7].f.y : acc[i][7].f.x) + bb[7];
            *(float4*)(C + tx * 8)     = v0;
            *(float4*)(C + tx * 8 + 4) = v1;
        }
    }
}

// ---------------------------------------------------------------------------
// Phase 2: persistent kernel; 4 independent groups x 32 blocks.
// Sub-barrier pipelining by k-quarters (as R11). CHANGE vs R11: GEMM is
// two-pass over the n-range with acc[8] instead of acc[16], cutting ~16 live
// registers so wv[32] f32x2 stays register-resident (no LDL spills).
// ---------------------------------------------------------------------------
__global__ __launch_bounds__(NTHR, 1) void lstm_persist_kernel(
    const float* __restrict__ Wh,     // [512, 2048]
    const float* __restrict__ h0,     // [64, 512]
    float* __restrict__ out)          // [64, 1024, 512]
{
    extern __shared__ char sm_raw[];
    float* Hs = (float*)sm_raw;                       // [256 kp][32] swizzled
    float* Ap = (float*)(sm_raw + 256 * 32 * 4);      // [8][16][64]

    const int tid  = threadIdx.x;
    const int lane = tid & 31;
    const int wrp  = tid >> 5;            // 0..15
    const int grp  = blockIdx.x >> 5;     // 0..3
    const int rank = blockIdx.x & 31;     // 0..31

    // GEMM thread mapping: ks = k-slice (64 k), ct = local gate column
    const int ct = tid & 63;              // 0..63
    const int ks = tid >> 6;              // 0..7
    const int qw = wrp >> 2;              // quarter this warp consumes
    const int gcol = (ct >> 4) * HH + 16 * rank + (ct & 15);

    // Wh slice in registers: wv[j] = (Wh[k0+2j][gcol], Wh[k0+2j+1][gcol])
    F2 wv[32];
    {
        const float* wp = Wh + (size_t)(ks * 64) * FH + gcol;
        #pragma unroll
        for (int j = 0; j < 32; ++j) {
            wv[j].f.x = __ldg(wp + (size_t)(2 * j) * FH);
            wv[j].f.y = __ldg(wp + (size_t)(2 * j + 1) * FH);
        }
    }

    // Staging map: warp stages 16 rows of its ks range; lane pair per row.
    const int srow = ks * 32 + (wrp & 1) * 16 + (lane >> 1);  // this lane's kp row
    const int shalf = lane & 1;                               // 64B half of row

    // Epilogue map: 2 threads per (n, u) item
    const int item = tid >> 1;
    const int kh   = tid & 1;
    const int en   = item >> 4;           // local batch 0..15
    const int eu   = item & 15;           // local unit 0..15
    const int ng   = NBG * grp + en;
    const int ug   = 16 * rank + eu;
    float creg = 0.f;

    unsigned* cnt_mine = &g_cnt[(grp * NQ + (rank >> 3)) * 32];  // arrive here
    unsigned* cnt_need = &g_cnt[(grp * NQ + qw) * 32];           // poll this

    // Prefetch xw for t = 0
    float xwv[4];
    if (kh == 0) {
        #pragma unroll
        for (int g = 0; g < 4; ++g)
            xwv[g] = g_xw[(size_t)(0 * NB + ng) * FH + g * HH + ug];
    }

    for (int t = 0; t < TT; ++t) {
        // ---- per-warp: wait for my quarter, stage my 2KB, pair-sync ----
        if (t > 0) {
            if (lane == 0) {
                const unsigned tgt = 8u * (unsigned)t;
                while (ld_acquire(cnt_need) < tgt) { }
            }
            __syncwarp();
            const float* src = &g_h2[(t + 1) & 1][grp][srow][shalf * 16];
            float* dstrow = Hs + srow * 32;
            const int sw = srow & 7;
            #pragma unroll
            for (int m = 0; m < 4; ++m) {
                int g = shalf * 4 + m;
                float4 v = __ldcg((const float4*)(src + m * 4));
                *(float4*)(dstrow + ((g ^ sw) * 4)) = v;
            }
        } else {
            // t == 0: gather h0 pairs into the swizzled layout
            const int sw = srow & 7;
            float* dstrow = Hs + srow * 32;
            #pragma unroll
            for (int ln = 0; ln < 8; ++ln) {
                int n = shalf * 8 + ln;
                float2 v = *(const float2*)(h0 + (size_t)(NBG * grp + n) * DD + 2 * srow);
                int g = shalf * 4 + (ln >> 1);
                *(float2*)(dstrow + ((g ^ sw) * 4) + (ln & 1) * 2) = v;
            }
        }
        asm volatile("bar.sync %0, 64;" :: "r"(1 + ks) : "memory");

        // ---- GEMM: 1 col x 16 n x 32 k-pairs, Wh in regs, TWO PASSES ----
        #pragma unroll
        for (int p = 0; p < 2; ++p) {
            F2 acc[8];
            #pragma unroll
            for (int n = 0; n < 8; ++n)
                acc[n].u = 0ull;

            #pragma unroll
            for (int j = 0; j < 32; ++j) {
                const int row = ks * 32 + j;
                const float* hrow = Hs + row * 32;
                const int sw = row & 7;
                #pragma unroll
                for (int q = 0; q < 4; ++q) {
                    const int qq = p * 4 + q;
                    float4 hq = *(const float4*)(hrow + ((qq ^ sw) * 4));
                    F2 lo, hi;
                    lo.f = make_float2(hq.x, hq.y);   // n=2qq   (even k, odd k)
                    hi.f = make_float2(hq.z, hq.w);   // n=2qq+1
                    FMA2(acc[2 * q],     lo, wv[j]);
                    FMA2(acc[2 * q + 1], hi, wv[j]);
                }
            }
            #pragma unroll
            for (int n = 0; n < 8; ++n)
                Ap[(ks * 16 + p * 8 + n) * 64 + ct] = acc[n].f.x + acc[n].f.y;
        }
        __syncthreads();

        // ---- reduce (2 threads/item over 8 k-slices) + gates ----
        float a[4];
        #pragma unroll
        for (int g = 0; g < 4; ++g) {
            float s = 0.f;
            #pragma unroll
            for (int k2 = 0; k2 < 4; ++k2)
                s += Ap[((kh * 4 + k2) * 16 + en) * 64 + g * 16 + eu];
            s += __shfl_xor_sync(0xFFFFFFFFu, s, 1);
            a[g] = s;
        }

        float hval = 0.f;
        if (kh == 0) {
            float ig = sigmoid_fast(a[0] + xwv[0]);
            float fg = sigmoid_fast(a[1] + xwv[1]);
            float og = sigmoid_fast(a[2] + xwv[2]);
            float gg = tanh_fast(a[3] + xwv[3]);
            creg = fmaf(fg, creg, ig * gg);
            hval = og * tanh_fast(creg);
            // paired layout: row = ug>>1, word = en*2 + (ug&1)
            g_h2[t & 1][grp][ug >> 1][en * 2 + (ug & 1)] = hval;
        }
        __syncthreads();    // Ap reuse safety + all h stores before arrive

        if (t + 1 < TT) {
            if (tid == 0)
                atom_release_add(cnt_mine);
            // ---- overlapped with other blocks' progress ----
            if (kh == 0) {
                out[(size_t)ng * TT * HH + (size_t)t * HH + ug] = hval;
                #pragma unroll
                for (int g = 0; g < 4; ++g)
                    xwv[g] = g_xw[(size_t)((t + 1) * NB + ng) * FH + g * HH + ug];
            }
        } else {
            if (kh == 0)
                out[(size_t)ng * TT * HH + (size_t)t * HH + ug] = hval;
        }
    }
}

// ---------------------------------------------------------------------------
extern "C" void kernel_launch(void* const* d_in, const int* in_sizes, int n_in,
                              void* d_out, int out_size)
{
    const float* x  = (const float*)d_in[0];   // [64, 1024, 512]
    const float* h0 = (const float*)d_in[1];   // [64, 512]
    const float* Wx = (const float*)d_in[2];   // [512, 2048]
    const float* Wh = (const float*)d_in[3];   // [512, 2048]
    const float* b  = (const float*)d_in[4];   // [2048]
    float* out = (float*)d_out;                // [64, 1024, 512]

    const int smem_bytes = 256 * 32 * 4 + 8 * 16 * 64 * 4;  // 32KB + 32KB
    cudaFuncSetAttribute(lstm_persist_kernel,
                         cudaFuncAttributeMaxDynamicSharedMemorySize, smem_bytes);

    dim3 g1(FH / 128, (NB * TT) / 128);        // (16, 512)
    sgemm_xw_kernel<<<g1, 256>>>(x, Wx, b);

    lstm_persist_kernel<<<GRID_R, NTHR, smem_bytes>>>(Wh, h0, out);
}

// round 16
// speedup vs baseline: 2.4250x; 1.8055x over previous
#include <cuda_runtime.h>
#include <cuda_bf16.h>
#include <math.h>
#include <stdint.h>

#define NB 64
#define TT 1024
#define DD 512
#define HH 512
#define FH 2048
#define GGRP 4
#define BPG 32
#define NBG 16
#define GRID_R (GGRP * BPG)
#define NTHR 512
#define NQ 4

// Scratch
__device__ float g_xw[(size_t)NB * TT * FH];
__device__ float g_h2[2][GGRP][DD / 2][2 * NBG];
__device__ unsigned g_cnt[GGRP * NQ * 32];
__device__ __nv_bfloat16 g_xhi[(size_t)NB * TT * DD];
__device__ __nv_bfloat16 g_xlo[(size_t)NB * TT * DD];
__device__ __nv_bfloat16 g_wthi[(size_t)FH * DD];   // WxT [n][k]
__device__ __nv_bfloat16 g_wtlo[(size_t)FH * DD];

union F2 { float2 f; unsigned long long u; };

#define FMA2(d, a, b) \
    asm("fma.rn.f32x2 %0, %1, %2, %3;" : "=l"((d).u) : "l"((a).u), "l"((b).u), "l"((d).u))

__device__ __forceinline__ float tanh_fast(float x) {
    float y;
    asm("tanh.approx.f32 %0, %1;" : "=f"(y) : "f"(x));
    return y;
}
__device__ __forceinline__ float sigmoid_fast(float x) {
    return fmaf(tanh_fast(0.5f * x), 0.5f, 0.5f);
}
__device__ __forceinline__ unsigned ld_acquire(const unsigned* p) {
    unsigned v;
    asm volatile("ld.acquire.gpu.global.u32 %0, [%1];" : "=r"(v) : "l"(p) : "memory");
    return v;
}
__device__ __forceinline__ void atom_release_add(unsigned* p) {
    unsigned old;
    asm volatile("atom.release.gpu.global.add.u32 %0, [%1], 1;"
                 : "=r"(old) : "l"(p) : "memory");
}
__device__ __forceinline__ uint32_t smem_u32(const void* p) {
    uint32_t a;
    asm("{ .reg .u64 t; cvta.to.shared.u64 t, %1; cvt.u32.u64 %0, t; }" : "=r"(a) : "l"(p));
    return a;
}
__device__ __forceinline__ void ldm_x4(uint32_t* r, uint32_t addr) {
    asm volatile("ldmatrix.sync.aligned.m8n8.x4.shared.b16 {%0,%1,%2,%3}, [%4];"
                 : "=r"(r[0]), "=r"(r[1]), "=r"(r[2]), "=r"(r[3]) : "r"(addr));
}
__device__ __forceinline__ void mma16816(float* d, const uint32_t* a,
                                         uint32_t b0, uint32_t b1) {
    asm volatile(
        "mma.sync.aligned.m16n8k16.row.col.f32.bf16.bf16.f32 "
        "{%0,%1,%2,%3}, {%4,%5,%6,%7}, {%8,%9}, {%0,%1,%2,%3};"
        : "+f"(d[0]), "+f"(d[1]), "+f"(d[2]), "+f"(d[3])
        : "r"(a[0]), "r"(a[1]), "r"(a[2]), "r"(a[3]), "r"(b0), "r"(b1));
}

// ---------------------------------------------------------------------------
// convert x -> bf16 hi/lo (also resets phase-2 barrier counters)
// ---------------------------------------------------------------------------
__global__ __launch_bounds__(256) void convert_x_kernel(const float* __restrict__ x)
{
    if (blockIdx.x == 0 && threadIdx.x < GGRP * NQ)
        g_cnt[threadIdx.x * 32] = 0u;
    size_t i = (size_t)(blockIdx.x * 256 + threadIdx.x) * 4;
    float4 v = *(const float4*)(x + i);
    __nv_bfloat16 h0 = __float2bfloat16_rn(v.x);
    __nv_bfloat16 h1 = __float2bfloat16_rn(v.y);
    __nv_bfloat16 h2 = __float2bfloat16_rn(v.z);
    __nv_bfloat16 h3 = __float2bfloat16_rn(v.w);
    __nv_bfloat162 hh0 = {h0, h1}, hh1 = {h2, h3};
    *(__nv_bfloat162*)(g_xhi + i)     = hh0;
    *(__nv_bfloat162*)(g_xhi + i + 2) = hh1;
    __nv_bfloat162 ll0 = {__float2bfloat16_rn(v.x - __bfloat162float(h0)),
                          __float2bfloat16_rn(v.y - __bfloat162float(h1))};
    __nv_bfloat162 ll1 = {__float2bfloat16_rn(v.z - __bfloat162float(h2)),
                          __float2bfloat16_rn(v.w - __bfloat162float(h3))};
    *(__nv_bfloat162*)(g_xlo + i)     = ll0;
    *(__nv_bfloat162*)(g_xlo + i + 2) = ll1;
}

// convert + transpose Wx[k][n] -> WxT_hi/lo[n][k]
__global__ __launch_bounds__(256) void convert_w_kernel(const float* __restrict__ Wx)
{
    int t = blockIdx.x * 256 + threadIdx.x;   // 0 .. FH*DD-1
    int k = t & (DD - 1);
    int n = t >> 9;
    float v = Wx[(size_t)k * FH + n];
    __nv_bfloat16 h = __float2bfloat16_rn(v);
    g_wthi[t] = h;
    g_wtlo[t] = __float2bfloat16_rn(v - __bfloat162float(h));
}

// ---------------------------------------------------------------------------
// Phase 1 on HMMA (mma.sync m16n8k16 bf16, sm_80-compatible — no 'a' target).
// Tile: BM=128 (x rows) x BN=64 (gate cols) x BK=64. 256 thr = 8 warps,
// warp tile 32x32 (2 m16 x 4 n8). bf16x3: D += Ah*Bh + Ah*Bl + Al*Bh.
// Smem rows 128B, SW128 xor-swizzled; ldmatrix x4 fragments.
// Grid (FH/64=32, 65536/128=512). Epilogue: +bias, store to g_xw [T,N,4H].
// ---------------------------------------------------------------------------
#define GSM_AHI 0
#define GSM_ALO 16384
#define GSM_BHI 32768
#define GSM_BLO 40960
#define GSM_TOTAL 49152

__global__ __launch_bounds__(256) void gemm_hmma_kernel(const float* __restrict__ bias)
{
    extern __shared__ char sm[];
    const int tid  = threadIdx.x;
    const int lane = tid & 31;
    const int wid  = tid >> 5;
    const int wm   = (wid & 3) * 32;      // warp m offset in tile
    const int wn   = (wid >> 2) * 32;     // warp n offset in tile
    const int col0 = blockIdx.x * 64;
    const int row0 = blockIdx.y * 128;
    const uint32_t sb = smem_u32(sm);

    float acc[2][4][4];                   // [m16 tile][n8 tile][frag]
    #pragma unroll
    for (int i = 0; i < 2; ++i)
        #pragma unroll
        for (int j = 0; j < 4; ++j)
            #pragma unroll
            for (int q = 0; q < 4; ++q)
                acc[i][j][q] = 0.f;

    // loaders: A: 2 thr/row (64B each); B: 4 thr/row (32B each)
    const int tr = tid >> 1, th = tid & 1;
    const int br = tid >> 2, bq = tid & 3;

    const int quad = lane >> 3, l7 = lane & 7;

    for (int c = 0; c < 8; ++c) {
        const int kc = c * 64;
        // ---- load chunk to smem (SW128 swizzle) ----
        {
            const uint4* sa = (const uint4*)(g_xhi + (size_t)(row0 + tr) * DD + kc + th * 32);
            const uint4* sl = (const uint4*)(g_xlo + (size_t)(row0 + tr) * DD + kc + th * 32);
            #pragma unroll
            for (int m = 0; m < 4; ++m) {
                int g = th * 4 + m;
                int off = tr * 128 + ((g ^ (tr & 7)) * 16);
                *(uint4*)(sm + GSM_AHI + off) = __ldg(sa + m);
                *(uint4*)(sm + GSM_ALO + off) = __ldg(sl + m);
            }
            const uint4* tb = (const uint4*)(g_wthi + (size_t)(col0 + br) * DD + kc + bq * 16);
            const uint4* tl = (const uint4*)(g_wtlo + (size_t)(col0 + br) * DD + kc + bq * 16);
            #pragma unroll
            for (int m = 0; m < 2; ++m) {
                int g = bq * 2 + m;
                int off = br * 128 + ((g ^ (br & 7)) * 16);
                *(uint4*)(sm + GSM_BHI + off) = __ldg(tb + m);
                *(uint4*)(sm + GSM_BLO + off) = __ldg(tl + m);
            }
        }
        __syncthreads();

        // ---- 4 k-steps of 16 ----
        #pragma unroll
        for (int ks = 0; ks < 4; ++ks) {
            const int g0 = ks * 2;
            uint32_t ah[2][4], al[2][4];
            #pragma unroll
            for (int mt = 0; mt < 2; ++mt) {
                int row = wm + mt * 16 + (quad & 1) * 8 + l7;
                int g = g0 + (quad >> 1);
                uint32_t adr = sb + GSM_AHI + row * 128 + ((g ^ (row & 7)) * 16);
                ldm_x4(ah[mt], adr);
                ldm_x4(al[mt], adr + (GSM_ALO - GSM_AHI));
            }
            uint32_t bh[2][4], bl[2][4];
            #pragma unroll
            for (int nt = 0; nt < 2; ++nt) {
                int row = wn + nt * 16 + (quad >> 1) * 8 + l7;
                int g = g0 + (quad & 1);
                uint32_t adr = sb + GSM_BHI + row * 128 + ((g ^ (row & 7)) * 16);
                ldm_x4(bh[nt], adr);
                ldm_x4(bl[nt], adr + (GSM_BLO - GSM_BHI));
            }
            #pragma unroll
            for (int mt = 0; mt < 2; ++mt) {
                #pragma unroll
                for (int nt = 0; nt < 2; ++nt) {
                    // n8 sub-tile 0: regs {0,1}; sub-tile 1: regs {2,3}
                    mma16816(acc[mt][nt * 2 + 0], ah[mt], bh[nt][0], bh[nt][1]);
                    mma16816(acc[mt][nt * 2 + 0], al[mt], bh[nt][0], bh[nt][1]);
                    mma16816(acc[mt][nt * 2 + 0], ah[mt], bl[nt][0], bl[nt][1]);
                    mma16816(acc[mt][nt * 2 + 1], ah[mt], bh[nt][2], bh[nt][3]);
                    mma16816(acc[mt][nt * 2 + 1], al[mt], bh[nt][2], bh[nt][3]);
                    mma16816(acc[mt][nt * 2 + 1], ah[mt], bl[nt][2], bl[nt][3]);
                }
            }
        }
        __syncthreads();
    }

    // ---- epilogue: +bias, write fp32 to g_xw in [T, N, 4H] order ----
    const int l4 = lane >> 2, l2 = (lane & 3) * 2;
    #pragma unroll
    for (int mt = 0; mt < 2; ++mt) {
        #pragma unroll
        for (int half = 0; half < 2; ++half) {
            int r = row0 + wm + mt * 16 + half * 8 + l4;
            int n = r >> 10;
            int t = r & 1023;
            float* C = g_xw + (size_t)(t * NB + n) * FH;
            #pragma unroll
            for (int nt8 = 0; nt8 < 4; ++nt8) {
                int col = col0 + wn + nt8 * 8 + l2;
                float2 v;
                v.x = acc[mt][nt8][half * 2 + 0] + __ldg(bias + col);
                v.y = acc[mt][nt8][half * 2 + 1] + __ldg(bias + col + 1);
                *(float2*)(C + col) = v;
            }
        }
    }
}

// ---------------------------------------------------------------------------
// Phase 2: persistent recurrence kernel — UNCHANGED from best (14.71 ms).
// ---------------------------------------------------------------------------
__global__ __launch_bounds__(NTHR, 1) void lstm_persist_kernel(
    const float* __restrict__ Wh,
    const float* __restrict__ h0,
    float* __restrict__ out)
{
    extern __shared__ char sm_raw[];
    float* Hs = (float*)sm_raw;
    float* Ap = (float*)(sm_raw + 256 * 32 * 4);

    const int tid  = threadIdx.x;
    const int lane = tid & 31;
    const int wrp  = tid >> 5;
    const int grp  = blockIdx.x >> 5;
    const int rank = blockIdx.x & 31;

    const int ct = tid & 63;
    const int ks = tid >> 6;
    const int qw = wrp >> 2;
    const int gcol = (ct >> 4) * HH + 16 * rank + (ct & 15);

    F2 wv[32];
    {
        const float* wp = Wh + (size_t)(ks * 64) * FH + gcol;
        #pragma unroll
        for (int j = 0; j < 32; ++j) {
            wv[j].f.x = __ldg(wp + (size_t)(2 * j) * FH);
            wv[j].f.y = __ldg(wp + (size_t)(2 * j + 1) * FH);
        }
    }

    const int srow = ks * 32 + (wrp & 1) * 16 + (lane >> 1);
    const int shalf = lane & 1;

    const int item = tid >> 1;
    const int kh   = tid & 1;
    const int en   = item >> 4;
    const int eu   = item & 15;
    const int ng   = NBG * grp + en;
    const int ug   = 16 * rank + eu;
    float creg = 0.f;

    unsigned* cnt_mine = &g_cnt[(grp * NQ + (rank >> 3)) * 32];
    unsigned* cnt_need = &g_cnt[(grp * NQ + qw) * 32];

    float xwv[4];
    if (kh == 0) {
        #pragma unroll
        for (int g = 0; g < 4; ++g)
            xwv[g] = g_xw[(size_t)(0 * NB + ng) * FH + g * HH + ug];
    }

    for (int t = 0; t < TT; ++t) {
        if (t > 0) {
            if (lane == 0) {
                const unsigned tgt = 8u * (unsigned)t;
                while (ld_acquire(cnt_need) < tgt) { }
            }
            __syncwarp();
            const float* src = &g_h2[(t + 1) & 1][grp][srow][shalf * 16];
            float* dstrow = Hs + srow * 32;
            const int sw = srow & 7;
            #pragma unroll
            for (int m = 0; m < 4; ++m) {
                int g = shalf * 4 + m;
                float4 v = __ldcg((const float4*)(src + m * 4));
                *(float4*)(dstrow + ((g ^ sw) * 4)) = v;
            }
        } else {
            const int sw = srow & 7;
            float* dstrow = Hs + srow * 32;
            #pragma unroll
            for (int ln = 0; ln < 8; ++ln) {
                int n = shalf * 8 + ln;
                float2 v = *(const float2*)(h0 + (size_t)(NBG * grp + n) * DD + 2 * srow);
                int g = shalf * 4 + (ln >> 1);
                *(float2*)(dstrow + ((g ^ sw) * 4) + (ln & 1) * 2) = v;
            }
        }
        asm volatile("bar.sync %0, 64;" :: "r"(1 + ks) : "memory");

        #pragma unroll
        for (int p = 0; p < 2; ++p) {
            F2 acc[8];
            #pragma unroll
            for (int n = 0; n < 8; ++n)
                acc[n].u = 0ull;

            #pragma unroll
            for (int j = 0; j < 32; ++j) {
                const int row = ks * 32 + j;
                const float* hrow = Hs + row * 32;
                const int sw = row & 7;
                #pragma unroll
                for (int q = 0; q < 4; ++q) {
                    const int qq = p * 4 + q;
                    float4 hq = *(const float4*)(hrow + ((qq ^ sw) * 4));
                    F2 lo, hi;
                    lo.f = make_float2(hq.x, hq.y);
                    hi.f = make_float2(hq.z, hq.w);
                    FMA2(acc[2 * q],     lo, wv[j]);
                    FMA2(acc[2 * q + 1], hi, wv[j]);
                }
            }
            #pragma unroll
            for (int n = 0; n < 8; ++n)
                Ap[(ks * 16 + p * 8 + n) * 64 + ct] = acc[n].f.x + acc[n].f.y;
        }
        __syncthreads();

        float a[4];
        #pragma unroll
        for (int g = 0; g < 4; ++g) {
            float s = 0.f;
            #pragma unroll
            for (int k2 = 0; k2 < 4; ++k2)
                s += Ap[((kh * 4 + k2) * 16 + en) * 64 + g * 16 + eu];
            s += __shfl_xor_sync(0xFFFFFFFFu, s, 1);
            a[g] = s;
        }

        float hval = 0.f;
        if (kh == 0) {
            float ig = sigmoid_fast(a[0] + xwv[0]);
            float fg = sigmoid_fast(a[1] + xwv[1]);
            float og = sigmoid_fast(a[2] + xwv[2]);
            float gg = tanh_fast(a[3] + xwv[3]);
            creg = fmaf(fg, creg, ig * gg);
            hval = og * tanh_fast(creg);
            g_h2[t & 1][grp][ug >> 1][en * 2 + (ug & 1)] = hval;
        }
        __syncthreads();

        if (t + 1 < TT) {
            if (tid == 0)
                atom_release_add(cnt_mine);
            if (kh == 0) {
                out[(size_t)ng * TT * HH + (size_t)t * HH + ug] = hval;
                #pragma unroll
                for (int g = 0; g < 4; ++g)
                    xwv[g] = g_xw[(size_t)((t + 1) * NB + ng) * FH + g * HH + ug];
            }
        } else {
            if (kh == 0)
                out[(size_t)ng * TT * HH + (size_t)t * HH + ug] = hval;
        }
    }
}

// ---------------------------------------------------------------------------
extern "C" void kernel_launch(void* const* d_in, const int* in_sizes, int n_in,
                              void* d_out, int out_size)
{
    const float* x  = (const float*)d_in[0];
    const float* h0 = (const float*)d_in[1];
    const float* Wx = (const float*)d_in[2];
    const float* Wh = (const float*)d_in[3];
    const float* b  = (const float*)d_in[4];
    float* out = (float*)d_out;

    cudaFuncSetAttribute(gemm_hmma_kernel,
                         cudaFuncAttributeMaxDynamicSharedMemorySize, GSM_TOTAL);
    const int smem_p2 = 256 * 32 * 4 + 8 * 16 * 64 * 4;
    cudaFuncSetAttribute(lstm_persist_kernel,
                         cudaFuncAttributeMaxDynamicSharedMemorySize, smem_p2);

    convert_x_kernel<<<(NB * TT * DD) / 4 / 256, 256>>>(x);
    convert_w_kernel<<<(FH * DD) / 256, 256>>>(Wx);

    dim3 g1(FH / 64, (NB * TT) / 128);    // (32, 512)
    gemm_hmma_kernel<<<g1, 256, GSM_TOTAL>>>(b);

    lstm_persist_kernel<<<GRID_R, NTHR, smem_p2>>>(Wh, h0, out);
}

// round 17
// speedup vs baseline: 3.5193x; 1.4513x over previous
#include <cuda_runtime.h>
#include <cuda_bf16.h>
#include <math.h>
#include <stdint.h>

#define NB 64
#define TT 1024
#define DD 512
#define HH 512
#define FH 2048
#define GGRP 4
#define BPG 32
#define NBG 16
#define GRID_R (GGRP * BPG)
#define NTHR 512
#define NQ 4

// Scratch
__device__ float g_xw[(size_t)NB * TT * FH];
__device__ unsigned g_cnt[GGRP * NQ * 32];
__device__ __nv_bfloat16 g_xhi[(size_t)NB * TT * DD];
__device__ __nv_bfloat16 g_xlo[(size_t)NB * TT * DD];
__device__ __nv_bfloat16 g_wthi[(size_t)FH * DD];   // WxT [n][k]
__device__ __nv_bfloat16 g_wtlo[(size_t)FH * DD];
// recurrence h exchange: bf16 hi/lo, [buf][grp][n][k]
__device__ __nv_bfloat16 g_hbhi[2][GGRP][NBG][DD];
__device__ __nv_bfloat16 g_hblo[2][GGRP][NBG][DD];

__device__ __forceinline__ float tanh_fast(float x) {
    float y;
    asm("tanh.approx.f32 %0, %1;" : "=f"(y) : "f"(x));
    return y;
}
__device__ __forceinline__ float sigmoid_fast(float x) {
    return fmaf(tanh_fast(0.5f * x), 0.5f, 0.5f);
}
__device__ __forceinline__ unsigned ld_acquire(const unsigned* p) {
    unsigned v;
    asm volatile("ld.acquire.gpu.global.u32 %0, [%1];" : "=r"(v) : "l"(p) : "memory");
    return v;
}
__device__ __forceinline__ void atom_release_add(unsigned* p) {
    unsigned old;
    asm volatile("atom.release.gpu.global.add.u32 %0, [%1], 1;"
                 : "=r"(old) : "l"(p) : "memory");
}
__device__ __forceinline__ uint32_t smem_u32(const void* p) {
    uint32_t a;
    asm("{ .reg .u64 t; cvta.to.shared.u64 t, %1; cvt.u32.u64 %0, t; }" : "=r"(a) : "l"(p));
    return a;
}
__device__ __forceinline__ void ldm_x4(uint32_t* r, uint32_t addr) {
    asm volatile("ldmatrix.sync.aligned.m8n8.x4.shared.b16 {%0,%1,%2,%3}, [%4];"
                 : "=r"(r[0]), "=r"(r[1]), "=r"(r[2]), "=r"(r[3]) : "r"(addr));
}
__device__ __forceinline__ void mma16816(float* d, const uint32_t* a,
                                         uint32_t b0, uint32_t b1) {
    asm volatile(
        "mma.sync.aligned.m16n8k16.row.col.f32.bf16.bf16.f32 "
        "{%0,%1,%2,%3}, {%4,%5,%6,%7}, {%8,%9}, {%0,%1,%2,%3};"
        : "+f"(d[0]), "+f"(d[1]), "+f"(d[2]), "+f"(d[3])
        : "r"(a[0]), "r"(a[1]), "r"(a[2]), "r"(a[3]), "r"(b0), "r"(b1));
}

// ---------------------------------------------------------------------------
// convert x -> bf16 hi/lo (also resets phase-2 barrier counters)
// ---------------------------------------------------------------------------
__global__ __launch_bounds__(256) void convert_x_kernel(const float* __restrict__ x)
{
    if (blockIdx.x == 0 && threadIdx.x < GGRP * NQ)
        g_cnt[threadIdx.x * 32] = 0u;
    size_t i = (size_t)(blockIdx.x * 256 + threadIdx.x) * 4;
    float4 v = *(const float4*)(x + i);
    __nv_bfloat16 h0 = __float2bfloat16_rn(v.x);
    __nv_bfloat16 h1 = __float2bfloat16_rn(v.y);
    __nv_bfloat16 h2 = __float2bfloat16_rn(v.z);
    __nv_bfloat16 h3 = __float2bfloat16_rn(v.w);
    __nv_bfloat162 hh0 = {h0, h1}, hh1 = {h2, h3};
    *(__nv_bfloat162*)(g_xhi + i)     = hh0;
    *(__nv_bfloat162*)(g_xhi + i + 2) = hh1;
    __nv_bfloat162 ll0 = {__float2bfloat16_rn(v.x - __bfloat162float(h0)),
                          __float2bfloat16_rn(v.y - __bfloat162float(h1))};
    __nv_bfloat162 ll1 = {__float2bfloat16_rn(v.z - __bfloat162float(h2)),
                          __float2bfloat16_rn(v.w - __bfloat162float(h3))};
    *(__nv_bfloat162*)(g_xlo + i)     = ll0;
    *(__nv_bfloat162*)(g_xlo + i + 2) = ll1;
}

__global__ __launch_bounds__(256) void convert_w_kernel(const float* __restrict__ Wx)
{
    int t = blockIdx.x * 256 + threadIdx.x;
    int k = t & (DD - 1);
    int n = t >> 9;
    float v = Wx[(size_t)k * FH + n];
    __nv_bfloat16 h = __float2bfloat16_rn(v);
    g_wthi[t] = h;
    g_wtlo[t] = __float2bfloat16_rn(v - __bfloat162float(h));
}

// ---------------------------------------------------------------------------
// Phase 1 on HMMA (UNCHANGED from R16 pass at 8.15 ms).
// ---------------------------------------------------------------------------
#define GSM_AHI 0
#define GSM_ALO 16384
#define GSM_BHI 32768
#define GSM_BLO 40960
#define GSM_TOTAL 49152

__global__ __launch_bounds__(256) void gemm_hmma_kernel(const float* __restrict__ bias)
{
    extern __shared__ char sm[];
    const int tid  = threadIdx.x;
    const int lane = tid & 31;
    const int wid  = tid >> 5;
    const int wm   = (wid & 3) * 32;
    const int wn   = (wid >> 2) * 32;
    const int col0 = blockIdx.x * 64;
    const int row0 = blockIdx.y * 128;
    const uint32_t sb = smem_u32(sm);

    float acc[2][4][4];
    #pragma unroll
    for (int i = 0; i < 2; ++i)
        #pragma unroll
        for (int j = 0; j < 4; ++j)
            #pragma unroll
            for (int q = 0; q < 4; ++q)
                acc[i][j][q] = 0.f;

    const int tr = tid >> 1, th = tid & 1;
    const int br = tid >> 2, bq = tid & 3;
    const int quad = lane >> 3, l7 = lane & 7;

    for (int c = 0; c < 8; ++c) {
        const int kc = c * 64;
        {
            const uint4* sa = (const uint4*)(g_xhi + (size_t)(row0 + tr) * DD + kc + th * 32);
            const uint4* sl = (const uint4*)(g_xlo + (size_t)(row0 + tr) * DD + kc + th * 32);
            #pragma unroll
            for (int m = 0; m < 4; ++m) {
                int g = th * 4 + m;
                int off = tr * 128 + ((g ^ (tr & 7)) * 16);
                *(uint4*)(sm + GSM_AHI + off) = __ldg(sa + m);
                *(uint4*)(sm + GSM_ALO + off) = __ldg(sl + m);
            }
            const uint4* tb = (const uint4*)(g_wthi + (size_t)(col0 + br) * DD + kc + bq * 16);
            const uint4* tl = (const uint4*)(g_wtlo + (size_t)(col0 + br) * DD + kc + bq * 16);
            #pragma unroll
            for (int m = 0; m < 2; ++m) {
                int g = bq * 2 + m;
                int off = br * 128 + ((g ^ (br & 7)) * 16);
                *(uint4*)(sm + GSM_BHI + off) = __ldg(tb + m);
                *(uint4*)(sm + GSM_BLO + off) = __ldg(tl + m);
            }
        }
        __syncthreads();

        #pragma unroll
        for (int ks = 0; ks < 4; ++ks) {
            const int g0 = ks * 2;
            uint32_t ah[2][4], al[2][4];
            #pragma unroll
            for (int mt = 0; mt < 2; ++mt) {
                int row = wm + mt * 16 + (quad & 1) * 8 + l7;
                int g = g0 + (quad >> 1);
                uint32_t adr = sb + GSM_AHI + row * 128 + ((g ^ (row & 7)) * 16);
                ldm_x4(ah[mt], adr);
                ldm_x4(al[mt], adr + (GSM_ALO - GSM_AHI));
            }
            uint32_t bh[2][4], bl[2][4];
            #pragma unroll
            for (int nt = 0; nt < 2; ++nt) {
                int row = wn + nt * 16 + (quad >> 1) * 8 + l7;
                int g = g0 + (quad & 1);
                uint32_t adr = sb + GSM_BHI + row * 128 + ((g ^ (row & 7)) * 16);
                ldm_x4(bh[nt], adr);
                ldm_x4(bl[nt], adr + (GSM_BLO - GSM_BHI));
            }
            #pragma unroll
            for (int mt = 0; mt < 2; ++mt) {
                #pragma unroll
                for (int nt = 0; nt < 2; ++nt) {
                    mma16816(acc[mt][nt * 2 + 0], ah[mt], bh[nt][0], bh[nt][1]);
                    mma16816(acc[mt][nt * 2 + 0], al[mt], bh[nt][0], bh[nt][1]);
                    mma16816(acc[mt][nt * 2 + 0], ah[mt], bl[nt][0], bl[nt][1]);
                    mma16816(acc[mt][nt * 2 + 1], ah[mt], bh[nt][2], bh[nt][3]);
                    mma16816(acc[mt][nt * 2 + 1], al[mt], bh[nt][2], bh[nt][3]);
                    mma16816(acc[mt][nt * 2 + 1], ah[mt], bl[nt][2], bl[nt][3]);
                }
            }
        }
        __syncthreads();
    }

    const int l4 = lane >> 2, l2 = (lane & 3) * 2;
    #pragma unroll
    for (int mt = 0; mt < 2; ++mt) {
        #pragma unroll
        for (int half = 0; half < 2; ++half) {
            int r = row0 + wm + mt * 16 + half * 8 + l4;
            int n = r >> 10;
            int t = r & 1023;
            float* C = g_xw + (size_t)(t * NB + n) * FH;
            #pragma unroll
            for (int nt8 = 0; nt8 < 4; ++nt8) {
                int col = col0 + wn + nt8 * 8 + l2;
                float2 v;
                v.x = acc[mt][nt8][half * 2 + 0] + __ldg(bias + col);
                v.y = acc[mt][nt8][half * 2 + 1] + __ldg(bias + col + 1);
                *(float2*)(C + col) = v;
            }
        }
    }
}

// ---------------------------------------------------------------------------
// Phase 2: persistent recurrence on HMMA.
// 4 groups x 32 blocks; block owns 16 units -> 64 gate cols, 16 batches.
// Wh slice bf16 hi/lo in smem (128KB, converted once, swizzled K-major rows).
// h exchanged as bf16 hi/lo [n][k]; per k-half (8 warps) staged to smem.
// 16 warps = 8 n8-tiles x 2 k-halves; 48 mma + 48 ldmatrix per warp per step.
// Smem: WHhi 64K | WHlo 64K | Hhi 16K | Hlo 16K | AP 8K = 168KB.
// ---------------------------------------------------------------------------
#define WH_HI 0
#define WH_LO 65536
#define H_HI  131072
#define H_LO  147456
#define AP_OFF 163840
#define SM2_TOTAL (AP_OFF + 8192)

__global__ __launch_bounds__(NTHR, 1) void lstm_persist_kernel(
    const float* __restrict__ Wh,
    const float* __restrict__ h0,
    float* __restrict__ out)
{
    extern __shared__ char sm[];
    float* AP = (float*)(sm + AP_OFF);
    const uint32_t sb = smem_u32(sm);

    const int tid  = threadIdx.x;
    const int lane = tid & 31;
    const int wrp  = tid >> 5;            // 0..15
    const int grp  = blockIdx.x >> 5;
    const int rank = blockIdx.x & 31;

    const int n8  = wrp & 7;              // warp's n8 tile (cols n8*8..+8)
    const int kh2 = wrp >> 3;             // warp's k-half (256 k)
    const int quad = lane >> 3, l7 = lane & 7;

    // ---- convert Wh slice -> smem bf16 hi/lo (once) ----
    {
        const int c = tid >> 3;           // local col 0..63
        const int kg0 = (tid & 7) * 8;    // 8 granules each
        const int gc = (c >> 4) * HH + 16 * rank + (c & 15);
        for (int gi = 0; gi < 8; ++gi) {
            int gk = kg0 + gi;
            int k0 = gk * 8;
            __nv_bfloat16 hi8[8], lo8[8];
            #pragma unroll
            for (int j = 0; j < 8; ++j) {
                float v = __ldg(Wh + (size_t)(k0 + j) * FH + gc);
                __nv_bfloat16 h = __float2bfloat16_rn(v);
                hi8[j] = h;
                lo8[j] = __float2bfloat16_rn(v - __bfloat162float(h));
            }
            int off = c * 1024 + ((gk ^ (c & 7)) * 16);
            *(uint4*)(sm + WH_HI + off) = *(uint4*)hi8;
            *(uint4*)(sm + WH_LO + off) = *(uint4*)lo8;
        }
    }
    __syncthreads();

    // staging map (within k-half group of 256 threads)
    const int t2 = tid & 255;
    const int hrow = t2 >> 4;             // 0..15 (batch row)
    const int gsub = t2 & 15;

    // epilogue map: tid<256 -> (en, eu)
    const int en = (tid >> 4) & 15;
    const int eu = tid & 15;
    const int ng = NBG * grp + en;
    const int ug = 16 * rank + eu;
    float creg = 0.f;

    unsigned* cnt_mine = &g_cnt[(grp * NQ + (rank >> 3)) * 32];

    float xwv[4];
    if (tid < 256) {
        #pragma unroll
        for (int g = 0; g < 4; ++g)
            xwv[g] = g_xw[(size_t)(0 * NB + ng) * FH + g * HH + ug];
    }

    for (int t = 0; t < TT; ++t) {
        // ---- wait for my k-half's two quarter counters ----
        if (t > 0) {
            if (lane < 2) {
                unsigned* cp = &g_cnt[(grp * NQ + kh2 * 2 + lane) * 32];
                const unsigned tgt = 8u * (unsigned)t;
                while (ld_acquire(cp) < tgt) { }
            }
            __syncwarp();
            // stage my k-half of h (hi+lo) into smem, swizzled
            #pragma unroll
            for (int e = 0; e < 2; ++e) {
                int gk = kh2 * 32 + gsub * 2 + e;
                uint4 vh = __ldcg((const uint4*)(&g_hbhi[(t + 1) & 1][grp][hrow][gk * 8]));
                uint4 vl = __ldcg((const uint4*)(&g_hblo[(t + 1) & 1][grp][hrow][gk * 8]));
                int off = hrow * 1024 + ((gk ^ (hrow & 7)) * 16);
                *(uint4*)(sm + H_HI + off) = vh;
                *(uint4*)(sm + H_LO + off) = vl;
            }
        } else {
            // t == 0: stage + convert from h0 (fp32)
            #pragma unroll
            for (int e = 0; e < 2; ++e) {
                int gk = kh2 * 32 + gsub * 2 + e;
                const float* hp = h0 + (size_t)(NBG * grp + hrow) * DD + gk * 8;
                __nv_bfloat16 hi8[8], lo8[8];
                #pragma unroll
                for (int j = 0; j < 8; ++j) {
                    float v = __ldg(hp + j);
                    __nv_bfloat16 hh = __float2bfloat16_rn(v);
                    hi8[j] = hh;
                    lo8[j] = __float2bfloat16_rn(v - __bfloat162float(hh));
                }
                int off = hrow * 1024 + ((gk ^ (hrow & 7)) * 16);
                *(uint4*)(sm + H_HI + off) = *(uint4*)hi8;
                *(uint4*)(sm + H_LO + off) = *(uint4*)lo8;
            }
        }
        asm volatile("bar.sync %0, 256;" :: "r"(1 + kh2) : "memory");

        // ---- GEMM: warp = n8 tile x k-half; 8 double-k-steps of 32 k ----
        float cacc[4] = {0.f, 0.f, 0.f, 0.f};
        #pragma unroll
        for (int ds = 0; ds < 8; ++ds) {
            const int g0 = kh2 * 32 + ds * 4;
            uint32_t bh[4], bl[4];
            {
                int rb = n8 * 8 + l7;
                int gb = g0 + (lane >> 3);
                uint32_t adr = sb + WH_HI + rb * 1024 + ((gb ^ (rb & 7)) * 16);
                ldm_x4(bh, adr);
                ldm_x4(bl, adr + (WH_LO - WH_HI));
            }
            #pragma unroll
            for (int s = 0; s < 2; ++s) {
                int arow = (quad & 1) * 8 + l7;
                int ga = g0 + s * 2 + (quad >> 1);
                uint32_t adr = sb + H_HI + arow * 1024 + ((ga ^ (arow & 7)) * 16);
                uint32_t ah[4], al[4];
                ldm_x4(ah, adr);
                ldm_x4(al, adr + (H_LO - H_HI));
                mma16816(cacc, ah, bh[2 * s], bh[2 * s + 1]);
                mma16816(cacc, al, bh[2 * s], bh[2 * s + 1]);
                mma16816(cacc, ah, bl[2 * s], bl[2 * s + 1]);
            }
        }

        // ---- store partials: AP[kh2][row][col] ----
        {
            int r0 = lane >> 2;
            int cc = n8 * 8 + (lane & 3) * 2;
            *(float2*)&AP[(kh2 * 16 + r0) * 64 + cc] = make_float2(cacc[0], cacc[1]);
            *(float2*)&AP[(kh2 * 16 + r0 + 8) * 64 + cc] = make_float2(cacc[2], cacc[3]);
        }
        __syncthreads();

        // ---- epilogue: reduce 2 k-halves + xw, gates, emit h ----
        float hval = 0.f;
        if (tid < 256) {
            float a[4];
            #pragma unroll
            for (int g = 0; g < 4; ++g) {
                int cc = g * 16 + eu;
                a[g] = AP[en * 64 + cc] + AP[(16 + en) * 64 + cc] + xwv[g];
            }
            float ig = sigmoid_fast(a[0]);
            float fg = sigmoid_fast(a[1]);
            float og = sigmoid_fast(a[2]);
            float gg = tanh_fast(a[3]);
            creg = fmaf(fg, creg, ig * gg);
            hval = og * tanh_fast(creg);
            __nv_bfloat16 hh = __float2bfloat16_rn(hval);
            g_hbhi[t & 1][grp][en][ug] = hh;
            g_hblo[t & 1][grp][en][ug] =
                __float2bfloat16_rn(hval - __bfloat162float(hh));
        }
        __syncthreads();   // h stores visible block-wide + AP read complete

        if (t + 1 < TT) {
            if (tid == 0)
                atom_release_add(cnt_mine);
            // overlapped with other blocks' arrivals:
            if (tid < 256) {
                out[(size_t)ng * TT * HH + (size_t)t * HH + ug] = hval;
                #pragma unroll
                for (int g = 0; g < 4; ++g)
                    xwv[g] = g_xw[(size_t)((t + 1) * NB + ng) * FH + g * HH + ug];
            }
        } else {
            if (tid < 256)
                out[(size_t)ng * TT * HH + (size_t)t * HH + ug] = hval;
        }
    }
}

// ---------------------------------------------------------------------------
extern "C" void kernel_launch(void* const* d_in, const int* in_sizes, int n_in,
                              void* d_out, int out_size)
{
    const float* x  = (const float*)d_in[0];
    const float* h0 = (const float*)d_in[1];
    const float* Wx = (const float*)d_in[2];
    const float* Wh = (const float*)d_in[3];
    const float* b  = (const float*)d_in[4];
    float* out = (float*)d_out;

    cudaFuncSetAttribute(gemm_hmma_kernel,
                         cudaFuncAttributeMaxDynamicSharedMemorySize, GSM_TOTAL);
    cudaFuncSetAttribute(lstm_persist_kernel,
                         cudaFuncAttributeMaxDynamicSharedMemorySize, SM2_TOTAL);

    convert_x_kernel<<<(NB * TT * DD) / 4 / 256, 256>>>(x);
    convert_w_kernel<<<(FH * DD) / 256, 256>>>(Wx);

    dim3 g1(FH / 64, (NB * TT) / 128);    // (32, 512)
    gemm_hmma_kernel<<<g1, 256, GSM_TOTAL>>>(b);

    lstm_persist_kernel<<<GRID_R, NTHR, SM2_TOTAL>>>(Wh, h0, out);
}